// round 16
// baseline (speedup 1.0000x reference)
#include <cuda_runtime.h>
#include <cuda_fp16.h>
#include <cstdint>

#define PP 32      // num networks
#define HH 128     // hidden
#define BB 32      // batch
#define TT 256     // seq len
#define NTHREADS 256
#define KTILES 10  // K = 160 = 10 x 16
#define NB 8       // batches per CTA

// B buffer: 8 batch-rows x PADW words (u32 = packed f16 k-pair).
// PADW=90 -> row stride 360 B, conflict-free for fragment loads.
// Only the h region (words 16..79, k-tiles 2..9) is used; X comes via registers.
#define PADW 90
#define BBUF (NB * PADW * 4)             // 2880 per buffer

// smem byte offsets
#define OFF_BIAS 0                        // 4*128 f32 = 2048
#define OFF_WOUT 2048                     // 128 f32 = 512
#define OFF_B0   2560                     // 2 buffers x BBUF = 5760
#define SMEM_BYTES (OFF_B0 + 2 * BBUF)    // 8320

// packed X scratch: [b][t][16 words], each word = f16 k-pair, fragment-layout
__device__ uint32_t Xp_g[BB * TT * 16];

__device__ __forceinline__ float tanha(float x) {
    float y; asm("tanh.approx.f32 %0, %1;" : "=f"(y) : "f"(x)); return y;
}
__device__ __forceinline__ float sigf(float x) {
    return fmaf(0.5f, tanha(0.5f * x), 0.5f);
}

__device__ __forceinline__ uint32_t pack_h2(float lo_k, float hi_k) {
    __half a = __float2half_rn(lo_k);
    __half b = __float2half_rn(hi_k);
    return (uint32_t)__half_as_ushort(a) | ((uint32_t)__half_as_ushort(b) << 16);
}

__device__ __forceinline__ void mma16816(float* d, const uint32_t* a, uint32_t b0, uint32_t b1) {
    asm volatile(
        "mma.sync.aligned.m16n8k16.row.col.f32.f16.f16.f32 "
        "{%0,%1,%2,%3}, {%4,%5,%6,%7}, {%8,%9}, {%0,%1,%2,%3};"
        : "+f"(d[0]), "+f"(d[1]), "+f"(d[2]), "+f"(d[3])
        : "r"(a[0]), "r"(a[1]), "r"(a[2]), "r"(a[3]), "r"(b0), "r"(b1));
}

__global__ void init_out_kernel(float* __restrict__ out, const float* __restrict__ b_out) {
    int i = blockIdx.x * blockDim.x + threadIdx.x;
    if (i < BB * TT * PP) out[i] = b_out[i & (PP - 1)];
}

// pack X into f16 word layout: word w of (b,t) holds k-pair at
// d0 = (w>>3)*16 + ((w&7)>>1)*2 + (w&1)*8
__global__ void xsplit_kernel(const float* __restrict__ X) {
    int i = blockIdx.x * blockDim.x + threadIdx.x;
    if (i >= BB * TT * 16) return;
    int w = i & 15;
    int bt = i >> 4;              // b*TT + t
    int d0 = ((w >> 3) * 16) + (((w & 7) >> 1) * 2) + ((w & 1) * 8);
    float v0 = X[(size_t)bt * PP + d0];
    float v1 = X[(size_t)bt * PP + d0 + 1];
    Xp_g[i] = pack_h2(v0, v1);
}

extern __shared__ char smem_c[];

__global__ void __launch_bounds__(NTHREADS, 1)
clstm_mma_kernel(const float* __restrict__ Wih,
                 const float* __restrict__ Whh,
                 const float* __restrict__ bih,
                 const float* __restrict__ bhh,
                 const float* __restrict__ Wout,
                 float* __restrict__ out)
{
    const int tid  = threadIdx.x;
    const int lane = tid & 31;
    const int wid  = tid >> 5;           // 8 warps; warp owns j in [wid*16, wid*16+16)
    const int r    = lane >> 2;          // fragment row group (0..7)
    const int tg   = lane & 3;           // fragment thread-in-group

    const int n  = blockIdx.x >> 2;      // network id
    const int bg = blockIdx.x & 3;       // batch group: global b = bg*8 + blocal
    const int j1 = wid * 16 + r;         // this thread's first j
    const int j2 = j1 + 8;               // second j

    // ---- zero both B buffers (h region must start at 0) ----
    {
        uint4 z = make_uint4(0, 0, 0, 0);
        for (int i = tid; i < 2 * BBUF / 16; i += NTHREADS)
            reinterpret_cast<uint4*>(smem_c + OFF_B0)[i] = z;
    }

    // ---- bias + wout for all 128 j ----
    for (int idx = tid; idx < 4 * HH; idx += NTHREADS) {
        int g = idx >> 7, j = idx & 127;
        int row = n * 4 * HH + g * HH + j;
        *reinterpret_cast<float*>(smem_c + OFF_BIAS + idx * 4) = bih[row] + bhh[row];
    }
    for (int idx = tid; idx < HH; idx += NTHREADS)
        *reinterpret_cast<float*>(smem_c + OFF_WOUT + idx * 4) = Wout[n * HH + idx];

    // ---- load A fragments (f16) into registers ----
    // m-tile mt = gate mt; tile rows 0..7 -> j1, rows 8..15 -> j2.
    uint32_t Ah[4][KTILES][4];
#pragma unroll
    for (int mt = 0; mt < 4; ++mt) {
        const size_t grow1 = (size_t)(n * 4 * HH + mt * HH + j1);
        const size_t grow2 = (size_t)(n * 4 * HH + mt * HH + j2);
#pragma unroll
        for (int kt = 0; kt < KTILES; ++kt) {
#pragma unroll
            for (int e = 0; e < 4; ++e) {
                // e: 0 -> (j1, k0), 1 -> (j2, k0), 2 -> (j1, k0+8), 3 -> (j2, k0+8)
                size_t grow = (e & 1) ? grow2 : grow1;
                int k = kt * 16 + tg * 2 + ((e >> 1) * 8);
                float v0, v1;
                if (k < PP) {
                    v0 = Wih[grow * PP + k];
                    v1 = Wih[grow * PP + k + 1];
                } else {
                    v0 = Whh[grow * HH + (k - PP)];
                    v1 = Whh[grow * HH + (k - PP) + 1];
                }
                Ah[mt][kt][e] = pack_h2(v0, v1);
            }
        }
    }

    // per-thread epilogue constants (reads ordered after writes above)
    __syncthreads();
    const float biasI1 = *reinterpret_cast<float*>(smem_c + OFF_BIAS + (0 * HH + j1) * 4);
    const float biasF1 = *reinterpret_cast<float*>(smem_c + OFF_BIAS + (1 * HH + j1) * 4);
    const float biasG1 = *reinterpret_cast<float*>(smem_c + OFF_BIAS + (2 * HH + j1) * 4);
    const float biasO1 = *reinterpret_cast<float*>(smem_c + OFF_BIAS + (3 * HH + j1) * 4);
    const float biasI2 = *reinterpret_cast<float*>(smem_c + OFF_BIAS + (0 * HH + j2) * 4);
    const float biasF2 = *reinterpret_cast<float*>(smem_c + OFF_BIAS + (1 * HH + j2) * 4);
    const float biasG2 = *reinterpret_cast<float*>(smem_c + OFF_BIAS + (2 * HH + j2) * 4);
    const float biasO2 = *reinterpret_cast<float*>(smem_c + OFF_BIAS + (3 * HH + j2) * 4);
    const float wout1  = *reinterpret_cast<float*>(smem_c + OFF_WOUT + j1 * 4);
    const float wout2  = *reinterpret_cast<float*>(smem_c + OFF_WOUT + j2 * 4);

    // h-write word offsets for j-pairs (even r packs (j, j+1)); k = 32 + j
    const int khe1 = PP + (j1 & ~1);
    const int khe2 = PP + (j2 & ~1);
    const uint32_t hw1 = (uint32_t)((khe1 >> 4) * 8 + ((khe1 >> 1) & 3) * 2 + ((khe1 >> 3) & 1)) * 4;
    const uint32_t hw2 = (uint32_t)((khe2 >> 4) * 8 + ((khe2 >> 1) & 3) * 2 + ((khe2 >> 3) & 1)) * 4;

    // X fragment source: this thread's batch row is r (b = bg*8 + r)
    const size_t xbase = ((size_t)(bg * NB + r) * TT) * 16 + tg * 2;

    // cell state: idx = jj*2 + cc -> (j = jj?j2:j1, b = tg*2+cc)
    float c[4] = {0.0f, 0.0f, 0.0f, 0.0f};

    // prologue: X fragments for t=0
    uint2 xf0 = *reinterpret_cast<const uint2*>(&Xp_g[xbase + 0 * 8]);
    uint2 xf1 = *reinterpret_cast<const uint2*>(&Xp_g[xbase + 1 * 8]);

    for (int t = 0; t < TT; ++t) {
        const char* bufp = smem_c + OFF_B0 + (t & 1) * BBUF;
        const uint32_t offB_next = (uint32_t)(OFF_B0 + ((t & 1) ^ 1) * BBUF);

        // ---- x-part MMAs (k-tiles 0..1) from registers — no h dependency ----
        float acc[4][4];
#pragma unroll
        for (int mt = 0; mt < 4; ++mt)
#pragma unroll
            for (int e = 0; e < 4; ++e) acc[mt][e] = 0.0f;
#pragma unroll
        for (int mt = 0; mt < 4; ++mt) mma16816(acc[mt], Ah[mt][0], xf0.x, xf0.y);
#pragma unroll
        for (int mt = 0; mt < 4; ++mt) mma16816(acc[mt], Ah[mt][1], xf1.x, xf1.y);

        // prefetch X(t+1) fragments
        int tn = (t + 1 < TT) ? (t + 1) : t;
        uint2 xf0n = *reinterpret_cast<const uint2*>(&Xp_g[xbase + (size_t)tn * 16 + 0 * 8]);
        uint2 xf1n = *reinterpret_cast<const uint2*>(&Xp_g[xbase + (size_t)tn * 16 + 1 * 8]);

        // h(t) stores from previous step's epilogue become visible
        __syncthreads();

        // ---- h-part MMAs (k-tiles 2..9) ----
#pragma unroll
        for (int kt = 2; kt < KTILES; ++kt) {
            uint32_t boff = (uint32_t)(r * PADW + kt * 8 + tg * 2) * 4;
            uint2 bh = *reinterpret_cast<const uint2*>(bufp + boff);
#pragma unroll
            for (int mt = 0; mt < 4; ++mt) mma16816(acc[mt], Ah[mt][kt], bh.x, bh.y);
        }

        // ---- fused epilogue straight from accumulators ----
        float pb0 = 0.0f, pb1 = 0.0f;    // head partials for b = tg*2, tg*2+1
#pragma unroll
        for (int jj = 0; jj < 2; ++jj) {
            const float bI = jj ? biasI2 : biasI1;
            const float bF = jj ? biasF2 : biasF1;
            const float bG = jj ? biasG2 : biasG1;
            const float bO = jj ? biasO2 : biasO1;
            const float wo = jj ? wout2 : wout1;
            const uint32_t hw = jj ? hw2 : hw1;
            uint32_t word_acc[2];
#pragma unroll
            for (int cc = 0; cc < 2; ++cc) {
                int idx = jj * 2 + cc;
                float gi = acc[0][idx] + bI;
                float gf = acc[1][idx] + bF;
                float gg = acc[2][idx] + bG;
                float go = acc[3][idx] + bO;
                float ii = sigf(gi);
                float ff = sigf(gf);
                float g2 = tanha(gg);
                float oo = sigf(go);
                float ncell = fmaf(ff, c[idx], ii * g2);
                c[idx] = ncell;
                float h = oo * tanha(ncell);

                uint32_t vh = (uint32_t)__half_as_ushort(__float2half_rn(h));
                // pair j (even) with j+1 (lane r+1, i.e. lane+4)
                uint32_t vhp = __shfl_down_sync(0xffffffffu, vh, 4);
                word_acc[cc] = vh | (vhp << 16);

                if (cc == 0) pb0 = fmaf(h, wo, pb0); else pb1 = fmaf(h, wo, pb1);
            }
            if (!(r & 1)) {
#pragma unroll
                for (int cc = 0; cc < 2; ++cc) {
                    uint32_t row = (uint32_t)(tg * 2 + cc) * (PADW * 4);
                    *reinterpret_cast<uint32_t*>(smem_c + offB_next + row + hw) = word_acc[cc];
                }
            }
        }

        // head: reduce over the warp's 16 j's (r axis: lane bits 2,3,4)
        pb0 += __shfl_xor_sync(0xffffffffu, pb0, 4);
        pb0 += __shfl_xor_sync(0xffffffffu, pb0, 8);
        pb0 += __shfl_xor_sync(0xffffffffu, pb0, 16);
        pb1 += __shfl_xor_sync(0xffffffffu, pb1, 4);
        pb1 += __shfl_xor_sync(0xffffffffu, pb1, 8);
        pb1 += __shfl_xor_sync(0xffffffffu, pb1, 16);
        if (r == 0) {
            int b0g = bg * NB + tg * 2;
            atomicAdd(&out[((size_t)b0g * TT + t) * PP + n], pb0);
            atomicAdd(&out[((size_t)(b0g + 1) * TT + t) * PP + n], pb1);
        }

        xf0 = xf0n;
        xf1 = xf1n;
    }
}

extern "C" void kernel_launch(void* const* d_in, const int* in_sizes, int n_in,
                              void* d_out, int out_size) {
    const float* X    = (const float*)d_in[0];
    const float* Wih  = (const float*)d_in[1];
    const float* Whh  = (const float*)d_in[2];
    const float* bih  = (const float*)d_in[3];
    const float* bhh  = (const float*)d_in[4];
    const float* Wout = (const float*)d_in[5];
    const float* bout = (const float*)d_in[6];
    float* out = (float*)d_out;

    cudaFuncSetAttribute(clstm_mma_kernel, cudaFuncAttributeMaxDynamicSharedMemorySize, SMEM_BYTES);

    init_out_kernel<<<(BB * TT * PP + 255) / 256, 256>>>(out, bout);
    xsplit_kernel<<<(BB * TT * 16 + 255) / 256, 256>>>(X);
    clstm_mma_kernel<<<PP * 4, NTHREADS, SMEM_BYTES>>>(Wih, Whh, bih, bhh, Wout, out);
}